// round 5
// baseline (speedup 1.0000x reference)
#include <cuda_runtime.h>
#include <cuda_bf16.h>
#include <cstdint>
#include <cstddef>

#define N_DIM     512
#define BATCH_DIM 16384
#define NROUND    511
#define NPAIR     256

// ---------------- scratch (static device globals; no runtime allocation) ----------------
__device__ __align__(16) int2          g_sched[NROUND * NPAIR];   // oriented+bucketed (i,j)
__device__ __align__(16) float2        g_cs  [NROUND * NPAIR];    // matching (cos, sin')
__device__ __align__(16) __nv_bfloat16 g_Uhi[N_DIM * N_DIM];
__device__ __align__(16) __nv_bfloat16 g_Ulo[N_DIM * N_DIM];
__device__ __align__(16) __nv_bfloat16 g_xhi[(size_t)BATCH_DIM * N_DIM];
__device__ __align__(16) __nv_bfloat16 g_xlo[(size_t)BATCH_DIM * N_DIM];

// ---------------- helpers ----------------
__device__ __forceinline__ uint32_t smem_u32(const void* p) {
    uint32_t a;
    asm("{ .reg .u64 t; cvta.to.shared.u64 t, %1; cvt.u32.u64 %0, t; }" : "=r"(a) : "l"(p));
    return a;
}

__device__ __forceinline__ void cp_async16(uint32_t s, const void* g) {
    asm volatile("cp.async.cg.shared.global [%0], [%1], 16;" :: "r"(s), "l"(g) : "memory");
}

__device__ __forceinline__ void ldm_x4(uint32_t* r, uint32_t addr) {
    asm volatile("ldmatrix.sync.aligned.m8n8.x4.shared.b16 {%0,%1,%2,%3}, [%4];"
                 : "=r"(r[0]), "=r"(r[1]), "=r"(r[2]), "=r"(r[3]) : "r"(addr));
}

__device__ __forceinline__ void mma16816(float* d, const uint32_t* a, uint32_t b0, uint32_t b1) {
    asm volatile(
        "mma.sync.aligned.m16n8k16.row.col.f32.bf16.bf16.f32 "
        "{%0,%1,%2,%3}, {%4,%5,%6,%7}, {%8,%9}, {%0,%1,%2,%3};"
        : "+f"(d[0]), "+f"(d[1]), "+f"(d[2]), "+f"(d[3])
        : "r"(a[0]), "r"(a[1]), "r"(a[2]), "r"(a[3]), "r"(b0), "r"(b1));
}

// ---------------- kernel 1: two-sided conflict-aware scheduling + sincos ----------------
// slot = occ*32 + bank(first elem)  ->  i-side accesses conflict-free per warp.
// Orientation of each pair is chosen (racy heuristic + claim table) so the j-side bank
// within each warp is mostly deduplicated as well.
__global__ void __launch_bounds__(NPAIR) sched_kernel(const int* __restrict__ blocks,
                                                      const float* __restrict__ angles) {
    __shared__ int  cnt[32];                 // per first-bank fill count (= warp row)
    __shared__ int  jflag[8 * 32];           // (warp, j-bank) claimed
    __shared__ unsigned char taken[NPAIR];
    __shared__ int  sfree[NPAIR];
    __shared__ int  nfree, ovfp;
    const int r = blockIdx.x;
    const int t = threadIdx.x;
    if (t < 32) cnt[t] = 0;
    jflag[t] = 0;                            // 256 == 8*32 exact
    taken[t] = 0;
    if (t == 0) { nfree = 0; ovfp = 0; }
    __syncthreads();

    const int i = blocks[(r * NPAIR + t) * 2];
    const int j = blocks[(r * NPAIR + t) * 2 + 1];
    float s, c;
    sincosf(angles[r * NPAIR + t], &s, &c);
    const int bi = i & 31, bj = j & 31;

    // racy pre-check: prefer the orientation whose (warp, other-bank) cell looks free
    const int oA = cnt[bi], oB = cnt[bj];
    const int fA = (oA < 8) && (jflag[oA * 32 + bj] == 0);
    const int fB = (oB < 8) && (jflag[oB * 32 + bi] == 0);
    int pref_first;
    if (fA != fB) pref_first = fA;
    else          pref_first = (oA <= oB);

    int slot = -1, swapped = 0;
    const int b0 = pref_first ? bi : bj;
    const int jb0 = pref_first ? bj : bi;
    int occ = atomicAdd(&cnt[b0], 1);
    if (occ < 8) {
        slot = occ * 32 + b0; swapped = pref_first ? 0 : 1;
        jflag[occ * 32 + jb0] = 1;
    } else {
        atomicSub(&cnt[b0], 1);
        const int b1 = pref_first ? bj : bi;
        const int jb1 = pref_first ? bi : bj;
        occ = atomicAdd(&cnt[b1], 1);
        if (occ < 8) {
            slot = occ * 32 + b1; swapped = pref_first ? 1 : 0;
            jflag[occ * 32 + jb1] = 1;
        } else atomicSub(&cnt[b1], 1);
    }
    if (slot >= 0) taken[slot] = 1;
    __syncthreads();
    if (!taken[t]) { int k = atomicAdd(&nfree, 1); sfree[k] = t; }
    __syncthreads();
    if (slot < 0) { int k = atomicAdd(&ovfp, 1); slot = sfree[k]; }

    int2 od; od.x = swapped ? j : i; od.y = swapped ? i : j;
    g_sched[r * NPAIR + slot] = od;
    g_cs  [r * NPAIR + slot] = make_float2(c, swapped ? -s : s);
}

// ---------------- kernel 2 (fused): build U rows  +  split x into bf16 hi/lo ----------------
__global__ void __launch_bounds__(256) build_split_kernel(const float4* __restrict__ x4) {
    const int t = threadIdx.x;
    if (blockIdx.x < N_DIM) {
        __shared__ float row[N_DIM];
        const int o = blockIdx.x;
        row[t]       = (t == o)       ? 1.0f : 0.0f;
        row[t + 256] = (t + 256 == o) ? 1.0f : 0.0f;
        int2   id = g_sched[t];
        float2 cs = g_cs[t];
        __syncthreads();
        for (int r = 0; r < NROUND; r++) {
            const int nidx = (r + 1 < NROUND) ? (r + 1) * NPAIR + t : t;
            const int2   id_n = g_sched[nidx];
            const float2 cs_n = g_cs[nidx];
            const float ui = row[id.x];
            const float uj = row[id.y];
            row[id.x] = fmaf(cs.x, ui, cs.y * uj);
            row[id.y] = fmaf(cs.x, uj, -(cs.y * ui));
            __syncthreads();
            id = id_n; cs = cs_n;
        }
        for (int cidx = t; cidx < N_DIM; cidx += 256) {
            const float v = row[cidx];
            const __nv_bfloat16 h = __float2bfloat16(v);
            g_Uhi[o * N_DIM + cidx] = h;
            g_Ulo[o * N_DIM + cidx] = __float2bfloat16(v - __bfloat162float(h));
        }
    } else {
        const int bs = blockIdx.x - N_DIM;                  // 0..511
        const int base = bs * 256 * 16;
        #pragma unroll 4
        for (int k = 0; k < 16; k++) {
            const int idx = base + k * 256 + t;
            const float4 v = x4[idx];
            __nv_bfloat16 h0 = __float2bfloat16(v.x);
            __nv_bfloat16 h1 = __float2bfloat16(v.y);
            __nv_bfloat16 h2 = __float2bfloat16(v.z);
            __nv_bfloat16 h3 = __float2bfloat16(v.w);
            __nv_bfloat162 a, b;
            a.x = h0; a.y = h1; b.x = h2; b.y = h3;
            ((__nv_bfloat162*)g_xhi)[2 * idx]     = a;
            ((__nv_bfloat162*)g_xhi)[2 * idx + 1] = b;
            a.x = __float2bfloat16(v.x - __bfloat162float(h0));
            a.y = __float2bfloat16(v.y - __bfloat162float(h1));
            b.x = __float2bfloat16(v.z - __bfloat162float(h2));
            b.y = __float2bfloat16(v.w - __bfloat162float(h3));
            ((__nv_bfloat162*)g_xlo)[2 * idx]     = a;
            ((__nv_bfloat162*)g_xlo)[2 * idx + 1] = b;
        }
    }
}

// ---------------- kernel 3: bf16x3 GEMM out = x @ U^T + bias ----------------
// CTA 128x128, 4 warps, warp tile 64x64. KC=64, 3-stage cp.async pipeline.
// 32 HMMA per 8 ldmatrix per ks-step: denser tensor-pipe feed than 32x64 warps.
#define KC        64
#define PITCH     144
#define ATILE     (128 * PITCH)
#define STAGE_SB  (2 * ATILE)
#define NSTAGE    3
#define GEMM_SMEM (NSTAGE * STAGE_SB)       // 110592 B
#define NCHUNK    24

__device__ __forceinline__ void issue_chunk(uint32_t sbase, int i, int m0, int n0, int tid) {
    if (i < NCHUNK) {
        const int phase = i >> 3;
        const int kc    = i & 7;
        const __nv_bfloat16* Asrc = (phase == 2) ? g_xlo : g_xhi;
        const __nv_bfloat16* Bsrc = (phase == 1) ? g_Ulo : g_Uhi;
        const __nv_bfloat16* gA = Asrc + (size_t)m0 * N_DIM + kc * KC;
        const __nv_bfloat16* gB = Bsrc + (size_t)n0 * N_DIM + kc * KC;
        const uint32_t stage = sbase + (uint32_t)(i % NSTAGE) * STAGE_SB;
        #pragma unroll
        for (int tt = 0; tt < 8; tt++) {                    // A: 1024 x 16B
            const int idx = tid + tt * 128;
            const int row = idx >> 3, seg = idx & 7;
            cp_async16(stage + (uint32_t)(row * PITCH + seg * 16),
                       gA + (size_t)row * N_DIM + seg * 8);
        }
        #pragma unroll
        for (int tt = 0; tt < 8; tt++) {                    // B: 1024 x 16B
            const int idx = tid + tt * 128;
            const int row = idx >> 3, seg = idx & 7;
            cp_async16(stage + ATILE + (uint32_t)(row * PITCH + seg * 16),
                       gB + (size_t)row * N_DIM + seg * 8);
        }
    }
    asm volatile("cp.async.commit_group;" ::: "memory");
}

__global__ void __launch_bounds__(128, 2) gemm_kernel(float* __restrict__ out,
                                                      const float* __restrict__ bias) {
    extern __shared__ char smem[];
    const uint32_t sb = smem_u32(smem);
    const int tid   = threadIdx.x;
    const int lane  = tid & 31;
    const int wid   = tid >> 5;
    const int warpM = wid & 1;
    const int warpN = wid >> 1;
    const int n0 = blockIdx.x * 128;
    const int m0 = blockIdx.y * 128;

    float acc[4][8][4];
    #pragma unroll
    for (int a = 0; a < 4; a++)
        #pragma unroll
        for (int b = 0; b < 8; b++)
            #pragma unroll
            for (int c = 0; c < 4; c++) acc[a][b][c] = 0.0f;

    const int lrow = lane & 15;
    const int loct = lane >> 4;

    issue_chunk(sb, 0, m0, n0, tid);
    issue_chunk(sb, 1, m0, n0, tid);

    for (int i = 0; i < NCHUNK; i++) {
        issue_chunk(sb, i + 2, m0, n0, tid);
        asm volatile("cp.async.wait_group 2;" ::: "memory");
        __syncthreads();

        const uint32_t stage = sb + (uint32_t)(i % NSTAGE) * STAGE_SB;
        const uint32_t sA = stage + (uint32_t)((warpM * 64 + lrow) * PITCH);
        const uint32_t sB = stage + ATILE + (uint32_t)((warpN * 64 + lrow) * PITCH);

        #pragma unroll
        for (int ks = 0; ks < 4; ks++) {
            const uint32_t koff = (uint32_t)(ks * 32 + loct * 16);
            uint32_t afr[4][4], bfr[4][4];
            #pragma unroll
            for (int mi = 0; mi < 4; mi++)
                ldm_x4(afr[mi], sA + (uint32_t)(mi * 16 * PITCH) + koff);
            #pragma unroll
            for (int nj = 0; nj < 4; nj++)
                ldm_x4(bfr[nj], sB + (uint32_t)(nj * 16 * PITCH) + koff);
            #pragma unroll
            for (int mi = 0; mi < 4; mi++)
                #pragma unroll
                for (int t = 0; t < 8; t++) {
                    const int nj = t >> 1, hl = t & 1;
                    mma16816(acc[mi][t], afr[mi], bfr[nj][hl], bfr[nj][hl + 2]);
                }
        }
        __syncthreads();
    }

    const int rbase = m0 + warpM * 64 + (lane >> 2);
    const int cbase = n0 + warpN * 64 + (lane & 3) * 2;
    #pragma unroll
    for (int t = 0; t < 8; t++) {
        const int col = cbase + t * 8;
        const float2 bv = __ldg((const float2*)&bias[col]);
        #pragma unroll
        for (int mi = 0; mi < 4; mi++) {
            const int r0 = rbase + mi * 16;
            float2 v0, v1;
            v0.x = acc[mi][t][0] + bv.x; v0.y = acc[mi][t][1] + bv.y;
            v1.x = acc[mi][t][2] + bv.x; v1.y = acc[mi][t][3] + bv.y;
            *(float2*)&out[(size_t)r0 * N_DIM + col]       = v0;
            *(float2*)&out[(size_t)(r0 + 8) * N_DIM + col] = v1;
        }
    }
}

// ---------------- launch ----------------
extern "C" void kernel_launch(void* const* d_in, const int* in_sizes, int n_in,
                              void* d_out, int out_size) {
    const float* x = nullptr;
    const float* angles = nullptr;
    const float* bias = nullptr;
    const int*   blocks = nullptr;
    for (int i = 0; i < n_in; i++) {
        const long sz = in_sizes[i];
        if      (sz == (long)BATCH_DIM * N_DIM)  x      = (const float*)d_in[i];
        else if (sz == (long)NROUND * NPAIR)     angles = (const float*)d_in[i];
        else if (sz == (long)N_DIM)              bias   = (const float*)d_in[i];
        else if (sz == (long)NROUND * NPAIR * 2) blocks = (const int*)d_in[i];
    }
    float* out = (float*)d_out;

    sched_kernel<<<NROUND, NPAIR>>>(blocks, angles);
    build_split_kernel<<<N_DIM + 512, 256>>>((const float4*)x);
    cudaFuncSetAttribute(gemm_kernel, cudaFuncAttributeMaxDynamicSharedMemorySize, GEMM_SMEM);
    gemm_kernel<<<dim3(4, 128), 128, GEMM_SMEM>>>(out, bias);
}

// round 6
// speedup vs baseline: 1.0938x; 1.0938x over previous
#include <cuda_runtime.h>
#include <cuda_fp16.h>
#include <cstdint>
#include <cstddef>

#define N_DIM     512
#define BATCH_DIM 16384
#define NROUND    511
#define NPAIR     256
#define RPB       4                 // rows per build block

// ---------------- scratch (static device globals; no runtime allocation) ----------------
__device__ __align__(16) uint32_t g_sched[NROUND * NPAIR];   // packed (i | j<<16), oriented
__device__ __align__(16) float2   g_cs  [NROUND * NPAIR];    // matching (cos, sin')
__device__ __align__(16) __half   g_Uh[N_DIM * N_DIM];
__device__ __align__(16) __half   g_Ul[N_DIM * N_DIM];
__device__ __align__(16) __half   g_xh[(size_t)BATCH_DIM * N_DIM];

// ---------------- helpers ----------------
__device__ __forceinline__ uint32_t smem_u32(const void* p) {
    uint32_t a;
    asm("{ .reg .u64 t; cvta.to.shared.u64 t, %1; cvt.u32.u64 %0, t; }" : "=r"(a) : "l"(p));
    return a;
}

__device__ __forceinline__ void cp_async16(uint32_t s, const void* g) {
    asm volatile("cp.async.cg.shared.global [%0], [%1], 16;" :: "r"(s), "l"(g) : "memory");
}

__device__ __forceinline__ void ldm_x4(uint32_t* r, uint32_t addr) {
    asm volatile("ldmatrix.sync.aligned.m8n8.x4.shared.b16 {%0,%1,%2,%3}, [%4];"
                 : "=r"(r[0]), "=r"(r[1]), "=r"(r[2]), "=r"(r[3]) : "r"(addr));
}

__device__ __forceinline__ void mma16816(float* d, const uint32_t* a, uint32_t b0, uint32_t b1) {
    asm volatile(
        "mma.sync.aligned.m16n8k16.row.col.f32.f16.f16.f32 "
        "{%0,%1,%2,%3}, {%4,%5,%6,%7}, {%8,%9}, {%0,%1,%2,%3};"
        : "+f"(d[0]), "+f"(d[1]), "+f"(d[2]), "+f"(d[3])
        : "r"(a[0]), "r"(a[1]), "r"(a[2]), "r"(a[3]), "r"(b0), "r"(b1));
}

// ---------------- kernel 1: conflict-aware scheduling + sincos ----------------
// slot = occ*32 + bank(first elem): i-side smem accesses conflict-free per warp.
__global__ void __launch_bounds__(NPAIR) sched_kernel(const int* __restrict__ blocks,
                                                      const float* __restrict__ angles) {
    __shared__ int  cnt[32];
    __shared__ int  jflag[8 * 32];
    __shared__ unsigned char taken[NPAIR];
    __shared__ int  sfree[NPAIR];
    __shared__ int  nfree, ovfp;
    const int r = blockIdx.x;
    const int t = threadIdx.x;
    if (t < 32) cnt[t] = 0;
    jflag[t] = 0;
    taken[t] = 0;
    if (t == 0) { nfree = 0; ovfp = 0; }
    __syncthreads();

    const int i = blocks[(r * NPAIR + t) * 2];
    const int j = blocks[(r * NPAIR + t) * 2 + 1];
    float s, c;
    sincosf(angles[r * NPAIR + t], &s, &c);
    const int bi = i & 31, bj = j & 31;

    const int oA = cnt[bi], oB = cnt[bj];
    const int fA = (oA < 8) && (jflag[oA * 32 + bj] == 0);
    const int fB = (oB < 8) && (jflag[oB * 32 + bi] == 0);
    int pref_first;
    if (fA != fB) pref_first = fA;
    else          pref_first = (oA <= oB);

    int slot = -1, swapped = 0;
    const int b0 = pref_first ? bi : bj;
    const int jb0 = pref_first ? bj : bi;
    int occ = atomicAdd(&cnt[b0], 1);
    if (occ < 8) {
        slot = occ * 32 + b0; swapped = pref_first ? 0 : 1;
        jflag[occ * 32 + jb0] = 1;
    } else {
        atomicSub(&cnt[b0], 1);
        const int b1 = pref_first ? bj : bi;
        const int jb1 = pref_first ? bi : bj;
        occ = atomicAdd(&cnt[b1], 1);
        if (occ < 8) {
            slot = occ * 32 + b1; swapped = pref_first ? 1 : 0;
            jflag[occ * 32 + jb1] = 1;
        } else atomicSub(&cnt[b1], 1);
    }
    if (slot >= 0) taken[slot] = 1;
    __syncthreads();
    if (!taken[t]) { int k = atomicAdd(&nfree, 1); sfree[k] = t; }
    __syncthreads();
    if (slot < 0) { int k = atomicAdd(&ovfp, 1); slot = sfree[k]; }

    const uint32_t ii = (uint32_t)(swapped ? j : i);
    const uint32_t jj = (uint32_t)(swapped ? i : j);
    g_sched[r * NPAIR + slot] = ii | (jj << 16);
    g_cs  [r * NPAIR + slot] = make_float2(c, swapped ? -s : s);
}

// ---------------- kernel 2 (fused): build 4 U rows/block  +  cast x to fp16 ----------------
// 4 rows per block amortizes the 2MB schedule stream 4x (L2-BW was the real bottleneck).
__global__ void __launch_bounds__(256) build_split_kernel(const float4* __restrict__ x4) {
    const int t = threadIdx.x;
    if (blockIdx.x < N_DIM / RPB) {
        __shared__ float rows[RPB][N_DIM];
        const int obase = blockIdx.x * RPB;
        #pragma unroll
        for (int q = 0; q < RPB; q++) {
            rows[q][t]       = (t == obase + q)       ? 1.0f : 0.0f;
            rows[q][t + 256] = (t + 256 == obase + q) ? 1.0f : 0.0f;
        }
        uint32_t id = g_sched[t];
        float2   cs = g_cs[t];
        __syncthreads();
        for (int r = 0; r < NROUND; r++) {
            const int nidx = (r + 1 < NROUND) ? (r + 1) * NPAIR + t : t;
            const uint32_t id_n = g_sched[nidx];
            const float2   cs_n = g_cs[nidx];
            const int i = (int)(id & 0xFFFFu);
            const int j = (int)(id >> 16);
            #pragma unroll
            for (int q = 0; q < RPB; q++) {
                const float ui = rows[q][i];
                const float uj = rows[q][j];
                rows[q][i] = fmaf(cs.x, ui, cs.y * uj);
                rows[q][j] = fmaf(cs.x, uj, -(cs.y * ui));
            }
            __syncthreads();
            id = id_n; cs = cs_n;
        }
        #pragma unroll
        for (int q = 0; q < RPB; q++)
            for (int c = t; c < N_DIM; c += 256) {
                const float v = rows[q][c];
                const __half h = __float2half(v);
                g_Uh[(obase + q) * N_DIM + c] = h;
                g_Ul[(obase + q) * N_DIM + c] = __float2half(v - __half2float(h));
            }
    } else {
        // cast x -> fp16 (no residual needed at fp16 precision)
        const int bs = blockIdx.x - N_DIM / RPB;            // 0..255
        const int base = bs * 8192;                         // float4 base; 256*8192 = 2^21 exact
        #pragma unroll 4
        for (int k = 0; k < 32; k++) {
            const int idx = base + k * 256 + t;
            const float4 v = x4[idx];
            __half2 a, b;
            a.x = __float2half(v.x); a.y = __float2half(v.y);
            b.x = __float2half(v.z); b.y = __float2half(v.w);
            ((__half2*)g_xh)[2 * idx]     = a;
            ((__half2*)g_xh)[2 * idx + 1] = b;
        }
    }
}

// ---------------- kernel 3: fp16x2 GEMM out = x @ U^T + bias ----------------
// CTA 128x128, 8 warps (warp 32x64). KC=64, stage = {A, Bh, Bl}; A loaded once per
// chunk and shared by both B products. 2-stage cp.async pipeline, 8 chunks.
#define KC        64
#define PITCH     144
#define TILE_SB   (128 * PITCH)             // 18432 B
#define STAGE_SB  (3 * TILE_SB)             // A + Bh + Bl = 55296 B
#define NSTAGE    2
#define GEMM_SMEM (NSTAGE * STAGE_SB)       // 110592 B
#define NCHUNK    8

__device__ __forceinline__ void issue_chunk(uint32_t sbase, int i, int m0, int n0, int tid) {
    if (i < NCHUNK) {
        const __half* gA  = g_xh + (size_t)m0 * N_DIM + i * KC;
        const __half* gBh = g_Uh + (size_t)n0 * N_DIM + i * KC;
        const __half* gBl = g_Ul + (size_t)n0 * N_DIM + i * KC;
        const uint32_t stage = sbase + (uint32_t)(i & 1) * STAGE_SB;
        #pragma unroll
        for (int tt = 0; tt < 4; tt++) {                    // each tile: 1024 x 16B
            const int idx = tid + tt * 256;
            const int row = idx >> 3, seg = idx & 7;
            const uint32_t soff = (uint32_t)(row * PITCH + seg * 16);
            const size_t goff = (size_t)row * N_DIM + seg * 8;
            cp_async16(stage + soff,               gA  + goff);
            cp_async16(stage + TILE_SB + soff,     gBh + goff);
            cp_async16(stage + 2 * TILE_SB + soff, gBl + goff);
        }
    }
    asm volatile("cp.async.commit_group;" ::: "memory");
}

__global__ void __launch_bounds__(256, 2) gemm_kernel(float* __restrict__ out,
                                                      const float* __restrict__ bias) {
    extern __shared__ char smem[];
    const uint32_t sb = smem_u32(smem);
    const int tid   = threadIdx.x;
    const int lane  = tid & 31;
    const int wid   = tid >> 5;
    const int warpM = wid & 3;
    const int warpN = wid >> 2;
    const int n0 = blockIdx.x * 128;
    const int m0 = blockIdx.y * 128;

    float acc[2][8][4];
    #pragma unroll
    for (int a = 0; a < 2; a++)
        #pragma unroll
        for (int b = 0; b < 8; b++)
            #pragma unroll
            for (int c = 0; c < 4; c++) acc[a][b][c] = 0.0f;

    const int lrow = lane & 15;
    const int loct = lane >> 4;

    issue_chunk(sb, 0, m0, n0, tid);
    issue_chunk(sb, 1, m0, n0, tid);

    for (int i = 0; i < NCHUNK; i++) {
        asm volatile("cp.async.wait_group 1;" ::: "memory");
        __syncthreads();

        const uint32_t stage = sb + (uint32_t)(i & 1) * STAGE_SB;
        const uint32_t sA  = stage + (uint32_t)((warpM * 32 + lrow) * PITCH);
        const uint32_t sBh = stage + TILE_SB + (uint32_t)((warpN * 64 + lrow) * PITCH);
        const uint32_t sBl = stage + 2 * TILE_SB + (uint32_t)((warpN * 64 + lrow) * PITCH);

        #pragma unroll
        for (int ks = 0; ks < 4; ks++) {
            const uint32_t koff = (uint32_t)(ks * 32 + loct * 16);
            uint32_t afr[2][4], bh[4][4], bl[4][4];
            #pragma unroll
            for (int mi = 0; mi < 2; mi++)
                ldm_x4(afr[mi], sA + (uint32_t)(mi * 16 * PITCH) + koff);
            #pragma unroll
            for (int nj = 0; nj < 4; nj++) {
                ldm_x4(bh[nj], sBh + (uint32_t)(nj * 16 * PITCH) + koff);
                ldm_x4(bl[nj], sBl + (uint32_t)(nj * 16 * PITCH) + koff);
            }
            #pragma unroll
            for (int mi = 0; mi < 2; mi++)
                #pragma unroll
                for (int t = 0; t < 8; t++) {
                    const int nj = t >> 1, hl = t & 1;
                    mma16816(acc[mi][t], afr[mi], bh[nj][hl], bh[nj][hl + 2]);
                    mma16816(acc[mi][t], afr[mi], bl[nj][hl], bl[nj][hl + 2]);
                }
        }
        __syncthreads();
        issue_chunk(sb, i + 2, m0, n0, tid);
    }

    const int rbase = m0 + warpM * 32 + (lane >> 2);
    const int cbase = n0 + warpN * 64 + (lane & 3) * 2;
    #pragma unroll
    for (int t = 0; t < 8; t++) {
        const int col = cbase + t * 8;
        const float2 bv = __ldg((const float2*)&bias[col]);
        #pragma unroll
        for (int mi = 0; mi < 2; mi++) {
            const int r0 = rbase + mi * 16;
            float2 v0, v1;
            v0.x = acc[mi][t][0] + bv.x; v0.y = acc[mi][t][1] + bv.y;
            v1.x = acc[mi][t][2] + bv.x; v1.y = acc[mi][t][3] + bv.y;
            *(float2*)&out[(size_t)r0 * N_DIM + col]       = v0;
            *(float2*)&out[(size_t)(r0 + 8) * N_DIM + col] = v1;
        }
    }
}

// ---------------- launch ----------------
extern "C" void kernel_launch(void* const* d_in, const int* in_sizes, int n_in,
                              void* d_out, int out_size) {
    const float* x = nullptr;
    const float* angles = nullptr;
    const float* bias = nullptr;
    const int*   blocks = nullptr;
    for (int i = 0; i < n_in; i++) {
        const long sz = in_sizes[i];
        if      (sz == (long)BATCH_DIM * N_DIM)  x      = (const float*)d_in[i];
        else if (sz == (long)NROUND * NPAIR)     angles = (const float*)d_in[i];
        else if (sz == (long)N_DIM)              bias   = (const float*)d_in[i];
        else if (sz == (long)NROUND * NPAIR * 2) blocks = (const int*)d_in[i];
    }
    float* out = (float*)d_out;

    sched_kernel<<<NROUND, NPAIR>>>(blocks, angles);
    build_split_kernel<<<N_DIM / RPB + 256, 256>>>((const float4*)x);
    cudaFuncSetAttribute(gemm_kernel, cudaFuncAttributeMaxDynamicSharedMemorySize, GEMM_SMEM);
    gemm_kernel<<<dim3(4, 128), 256, GEMM_SMEM>>>(out, bias);
}

// round 7
// speedup vs baseline: 1.2456x; 1.1388x over previous
#include <cuda_runtime.h>
#include <cuda_fp16.h>
#include <cstdint>
#include <cstddef>

#define N_DIM     512
#define BATCH_DIM 16384
#define NROUND    511
#define NPAIR     256
#define RPB       4                 // rows per build block

// ---------------- scratch (static device globals; no runtime allocation) ----------------
__device__ __align__(16) uint32_t g_sched[NROUND * NPAIR];   // packed (i | j<<16), oriented
__device__ __align__(16) float2   g_cs  [NROUND * NPAIR];    // matching (cos, sin')
__device__ __align__(16) __half   g_Uh[N_DIM * N_DIM];
__device__ __align__(16) __half   g_xh[(size_t)BATCH_DIM * N_DIM];

// ---------------- helpers ----------------
__device__ __forceinline__ uint32_t smem_u32(const void* p) {
    uint32_t a;
    asm("{ .reg .u64 t; cvta.to.shared.u64 t, %1; cvt.u32.u64 %0, t; }" : "=r"(a) : "l"(p));
    return a;
}

__device__ __forceinline__ void cp_async16(uint32_t s, const void* g) {
    asm volatile("cp.async.cg.shared.global [%0], [%1], 16;" :: "r"(s), "l"(g) : "memory");
}

__device__ __forceinline__ void ldm_x4(uint32_t* r, uint32_t addr) {
    asm volatile("ldmatrix.sync.aligned.m8n8.x4.shared.b16 {%0,%1,%2,%3}, [%4];"
                 : "=r"(r[0]), "=r"(r[1]), "=r"(r[2]), "=r"(r[3]) : "r"(addr));
}

__device__ __forceinline__ void mma16816(float* d, const uint32_t* a, uint32_t b0, uint32_t b1) {
    asm volatile(
        "mma.sync.aligned.m16n8k16.row.col.f32.f16.f16.f32 "
        "{%0,%1,%2,%3}, {%4,%5,%6,%7}, {%8,%9}, {%0,%1,%2,%3};"
        : "+f"(d[0]), "+f"(d[1]), "+f"(d[2]), "+f"(d[3])
        : "r"(a[0]), "r"(a[1]), "r"(a[2]), "r"(a[3]), "r"(b0), "r"(b1));
}

// ---------------- kernel 1: conflict-aware scheduling + sincos ----------------
__global__ void __launch_bounds__(NPAIR) sched_kernel(const int* __restrict__ blocks,
                                                      const float* __restrict__ angles) {
    __shared__ int  cnt[32];
    __shared__ int  jflag[8 * 32];
    __shared__ unsigned char taken[NPAIR];
    __shared__ int  sfree[NPAIR];
    __shared__ int  nfree, ovfp;
    const int r = blockIdx.x;
    const int t = threadIdx.x;
    if (t < 32) cnt[t] = 0;
    jflag[t] = 0;
    taken[t] = 0;
    if (t == 0) { nfree = 0; ovfp = 0; }
    __syncthreads();

    const int i = blocks[(r * NPAIR + t) * 2];
    const int j = blocks[(r * NPAIR + t) * 2 + 1];
    float s, c;
    sincosf(angles[r * NPAIR + t], &s, &c);
    const int bi = i & 31, bj = j & 31;

    const int oA = cnt[bi], oB = cnt[bj];
    const int fA = (oA < 8) && (jflag[oA * 32 + bj] == 0);
    const int fB = (oB < 8) && (jflag[oB * 32 + bi] == 0);
    int pref_first;
    if (fA != fB) pref_first = fA;
    else          pref_first = (oA <= oB);

    int slot = -1, swapped = 0;
    const int b0 = pref_first ? bi : bj;
    const int jb0 = pref_first ? bj : bi;
    int occ = atomicAdd(&cnt[b0], 1);
    if (occ < 8) {
        slot = occ * 32 + b0; swapped = pref_first ? 0 : 1;
        jflag[occ * 32 + jb0] = 1;
    } else {
        atomicSub(&cnt[b0], 1);
        const int b1 = pref_first ? bj : bi;
        const int jb1 = pref_first ? bi : bj;
        occ = atomicAdd(&cnt[b1], 1);
        if (occ < 8) {
            slot = occ * 32 + b1; swapped = pref_first ? 1 : 0;
            jflag[occ * 32 + jb1] = 1;
        } else atomicSub(&cnt[b1], 1);
    }
    if (slot >= 0) taken[slot] = 1;
    __syncthreads();
    if (!taken[t]) { int k = atomicAdd(&nfree, 1); sfree[k] = t; }
    __syncthreads();
    if (slot < 0) { int k = atomicAdd(&ovfp, 1); slot = sfree[k]; }

    const uint32_t ii = (uint32_t)(swapped ? j : i);
    const uint32_t jj = (uint32_t)(swapped ? i : j);
    g_sched[r * NPAIR + slot] = ii | (jj << 16);
    g_cs  [r * NPAIR + slot] = make_float2(c, swapped ? -s : s);
}

// ---------------- kernel 2 (fused): build 4 U rows/block  +  cast x to fp16 ----------------
__global__ void __launch_bounds__(256) build_split_kernel(const float4* __restrict__ x4) {
    const int t = threadIdx.x;
    if (blockIdx.x < N_DIM / RPB) {
        __shared__ float rows[RPB][N_DIM];
        const int obase = blockIdx.x * RPB;
        #pragma unroll
        for (int q = 0; q < RPB; q++) {
            rows[q][t]       = (t == obase + q)       ? 1.0f : 0.0f;
            rows[q][t + 256] = (t + 256 == obase + q) ? 1.0f : 0.0f;
        }
        uint32_t id = g_sched[t];
        float2   cs = g_cs[t];
        __syncthreads();
        for (int r = 0; r < NROUND; r++) {
            const int nidx = (r + 1 < NROUND) ? (r + 1) * NPAIR + t : t;
            const uint32_t id_n = g_sched[nidx];
            const float2   cs_n = g_cs[nidx];
            const int i = (int)(id & 0xFFFFu);
            const int j = (int)(id >> 16);
            #pragma unroll
            for (int q = 0; q < RPB; q++) {
                const float ui = rows[q][i];
                const float uj = rows[q][j];
                rows[q][i] = fmaf(cs.x, ui, cs.y * uj);
                rows[q][j] = fmaf(cs.x, uj, -(cs.y * ui));
            }
            __syncthreads();
            id = id_n; cs = cs_n;
        }
        #pragma unroll
        for (int q = 0; q < RPB; q++)
            for (int c = t; c < N_DIM; c += 256)
                g_Uh[(obase + q) * N_DIM + c] = __float2half(rows[q][c]);
    } else {
        // cast x -> fp16
        const int bs = blockIdx.x - N_DIM / RPB;            // 0..255
        const int base = bs * 8192;                         // 256*8192 = 2^21 float4 exact
        #pragma unroll 4
        for (int k = 0; k < 32; k++) {
            const int idx = base + k * 256 + t;
            const float4 v = x4[idx];
            __half2 a, b;
            a.x = __float2half(v.x); a.y = __float2half(v.y);
            b.x = __float2half(v.z); b.y = __float2half(v.w);
            ((__half2*)g_xh)[2 * idx]     = a;
            ((__half2*)g_xh)[2 * idx + 1] = b;
        }
    }
}

// ---------------- kernel 3: single fp16 GEMM out = x @ U^T + bias ----------------
// CTA 128x128, 8 warps (warp 32x64). KC=64, 3-stage cp.async pipeline, 8 chunks.
#define KC        64
#define PITCH     144
#define TILE_SB   (128 * PITCH)             // 18432 B
#define STAGE_SB  (2 * TILE_SB)             // A + B = 36864 B
#define NSTAGE    3
#define GEMM_SMEM (NSTAGE * STAGE_SB)       // 110592 B
#define NCHUNK    8

__device__ __forceinline__ void issue_chunk(uint32_t sbase, int i, int m0, int n0, int tid) {
    if (i < NCHUNK) {
        const __half* gA = g_xh + (size_t)m0 * N_DIM + i * KC;
        const __half* gB = g_Uh + (size_t)n0 * N_DIM + i * KC;
        const uint32_t stage = sbase + (uint32_t)(i % NSTAGE) * STAGE_SB;
        #pragma unroll
        for (int tt = 0; tt < 4; tt++) {                    // each tile: 1024 x 16B
            const int idx = tid + tt * 256;
            const int row = idx >> 3, seg = idx & 7;
            const uint32_t soff = (uint32_t)(row * PITCH + seg * 16);
            const size_t goff = (size_t)row * N_DIM + seg * 8;
            cp_async16(stage + soff,           gA + goff);
            cp_async16(stage + TILE_SB + soff, gB + goff);
        }
    }
    asm volatile("cp.async.commit_group;" ::: "memory");
}

__global__ void __launch_bounds__(256, 2) gemm_kernel(float* __restrict__ out,
                                                      const float* __restrict__ bias) {
    extern __shared__ char smem[];
    const uint32_t sb = smem_u32(smem);
    const int tid   = threadIdx.x;
    const int lane  = tid & 31;
    const int wid   = tid >> 5;
    const int warpM = wid & 3;
    const int warpN = wid >> 2;
    const int n0 = blockIdx.x * 128;
    const int m0 = blockIdx.y * 128;

    float acc[2][8][4];
    #pragma unroll
    for (int a = 0; a < 2; a++)
        #pragma unroll
        for (int b = 0; b < 8; b++)
            #pragma unroll
            for (int c = 0; c < 4; c++) acc[a][b][c] = 0.0f;

    const int lrow = lane & 15;
    const int loct = lane >> 4;

    issue_chunk(sb, 0, m0, n0, tid);
    issue_chunk(sb, 1, m0, n0, tid);

    for (int i = 0; i < NCHUNK; i++) {
        issue_chunk(sb, i + 2, m0, n0, tid);
        asm volatile("cp.async.wait_group 2;" ::: "memory");
        __syncthreads();

        const uint32_t stage = sb + (uint32_t)(i % NSTAGE) * STAGE_SB;
        const uint32_t sA = stage + (uint32_t)((warpM * 32 + lrow) * PITCH);
        const uint32_t sB = stage + TILE_SB + (uint32_t)((warpN * 64 + lrow) * PITCH);

        #pragma unroll
        for (int ks = 0; ks < 4; ks++) {
            const uint32_t koff = (uint32_t)(ks * 32 + loct * 16);
            uint32_t afr[2][4], bfr[4][4];
            #pragma unroll
            for (int mi = 0; mi < 2; mi++)
                ldm_x4(afr[mi], sA + (uint32_t)(mi * 16 * PITCH) + koff);
            #pragma unroll
            for (int nj = 0; nj < 4; nj++)
                ldm_x4(bfr[nj], sB + (uint32_t)(nj * 16 * PITCH) + koff);
            #pragma unroll
            for (int mi = 0; mi < 2; mi++)
                #pragma unroll
                for (int t = 0; t < 8; t++) {
                    const int nj = t >> 1, hl = t & 1;
                    mma16816(acc[mi][t], afr[mi], bfr[nj][hl], bfr[nj][hl + 2]);
                }
        }
        __syncthreads();
    }

    const int rbase = m0 + warpM * 32 + (lane >> 2);
    const int cbase = n0 + warpN * 64 + (lane & 3) * 2;
    #pragma unroll
    for (int t = 0; t < 8; t++) {
        const int col = cbase + t * 8;
        const float2 bv = __ldg((const float2*)&bias[col]);
        #pragma unroll
        for (int mi = 0; mi < 2; mi++) {
            const int r0 = rbase + mi * 16;
            float2 v0, v1;
            v0.x = acc[mi][t][0] + bv.x; v0.y = acc[mi][t][1] + bv.y;
            v1.x = acc[mi][t][2] + bv.x; v1.y = acc[mi][t][3] + bv.y;
            *(float2*)&out[(size_t)r0 * N_DIM + col]       = v0;
            *(float2*)&out[(size_t)(r0 + 8) * N_DIM + col] = v1;
        }
    }
}

// ---------------- launch ----------------
extern "C" void kernel_launch(void* const* d_in, const int* in_sizes, int n_in,
                              void* d_out, int out_size) {
    const float* x = nullptr;
    const float* angles = nullptr;
    const float* bias = nullptr;
    const int*   blocks = nullptr;
    for (int i = 0; i < n_in; i++) {
        const long sz = in_sizes[i];
        if      (sz == (long)BATCH_DIM * N_DIM)  x      = (const float*)d_in[i];
        else if (sz == (long)NROUND * NPAIR)     angles = (const float*)d_in[i];
        else if (sz == (long)N_DIM)              bias   = (const float*)d_in[i];
        else if (sz == (long)NROUND * NPAIR * 2) blocks = (const int*)d_in[i];
    }
    float* out = (float*)d_out;

    sched_kernel<<<NROUND, NPAIR>>>(blocks, angles);
    build_split_kernel<<<N_DIM / RPB + 256, 256>>>((const float4*)x);
    cudaFuncSetAttribute(gemm_kernel, cudaFuncAttributeMaxDynamicSharedMemorySize, GEMM_SMEM);
    gemm_kernel<<<dim3(4, 128), 256, GEMM_SMEM>>>(out, bias);
}

// round 10
// speedup vs baseline: 1.5655x; 1.2568x over previous
#include <cuda_runtime.h>
#include <cuda_fp16.h>
#include <cstdint>
#include <cstddef>

#define N_DIM     512
#define BATCH_DIM 16384
#define NROUND    511
#define NPAIR     256
#define RPB       4                 // rows per build block
#define SEG0_END  256               // segment 0 = rounds [0,256), segment 1 = [256,511)

// ---------------- scratch (static device globals; no runtime allocation) ----------------
__device__ __align__(16) uint32_t g_sched[NROUND * NPAIR];   // packed (i | j<<16), oriented
__device__ __align__(16) float2   g_cs  [NROUND * NPAIR];    // matching (cos, sin')
__device__ __align__(16) float    g_V0[N_DIM * N_DIM];       // product of rounds [0,256)
__device__ __align__(16) float    g_V1[N_DIM * N_DIM];       // product of rounds [256,511)
__device__ __align__(16) __half   g_Uh[N_DIM * N_DIM];       // U = V0*V1, fp16
__device__ __align__(16) __half   g_xh[(size_t)BATCH_DIM * N_DIM];

// ---------------- helpers ----------------
__device__ __forceinline__ uint32_t smem_u32(const void* p) {
    uint32_t a;
    asm("{ .reg .u64 t; cvta.to.shared.u64 t, %1; cvt.u32.u64 %0, t; }" : "=r"(a) : "l"(p));
    return a;
}

__device__ __forceinline__ void cp_async16(uint32_t s, const void* g) {
    asm volatile("cp.async.cg.shared.global [%0], [%1], 16;" :: "r"(s), "l"(g) : "memory");
}

__device__ __forceinline__ void ldm_x4(uint32_t* r, uint32_t addr) {
    asm volatile("ldmatrix.sync.aligned.m8n8.x4.shared.b16 {%0,%1,%2,%3}, [%4];"
                 : "=r"(r[0]), "=r"(r[1]), "=r"(r[2]), "=r"(r[3]) : "r"(addr));
}

__device__ __forceinline__ void mma16816(float* d, const uint32_t* a, uint32_t b0, uint32_t b1) {
    asm volatile(
        "mma.sync.aligned.m16n8k16.row.col.f32.f16.f16.f32 "
        "{%0,%1,%2,%3}, {%4,%5,%6,%7}, {%8,%9}, {%0,%1,%2,%3};"
        : "+f"(d[0]), "+f"(d[1]), "+f"(d[2]), "+f"(d[3])
        : "r"(a[0]), "r"(a[1]), "r"(a[2]), "r"(a[3]), "r"(b0), "r"(b1));
}

// ---------------- kernel 1: conflict-aware scheduling + sincos ----------------
__global__ void __launch_bounds__(NPAIR) sched_kernel(const int* __restrict__ blocks,
                                                      const float* __restrict__ angles) {
    __shared__ int  cnt[32];
    __shared__ int  jflag[8 * 32];
    __shared__ unsigned char taken[NPAIR];
    __shared__ int  sfree[NPAIR];
    __shared__ int  nfree, ovfp;
    const int r = blockIdx.x;
    const int t = threadIdx.x;
    if (t < 32) cnt[t] = 0;
    jflag[t] = 0;
    taken[t] = 0;
    if (t == 0) { nfree = 0; ovfp = 0; }
    __syncthreads();

    const int i = blocks[(r * NPAIR + t) * 2];
    const int j = blocks[(r * NPAIR + t) * 2 + 1];
    float s, c;
    sincosf(angles[r * NPAIR + t], &s, &c);
    const int bi = i & 31, bj = j & 31;

    const int oA = cnt[bi], oB = cnt[bj];
    const int fA = (oA < 8) && (jflag[oA * 32 + bj] == 0);
    const int fB = (oB < 8) && (jflag[oB * 32 + bi] == 0);
    int pref_first;
    if (fA != fB) pref_first = fA;
    else          pref_first = (oA <= oB);

    int slot = -1, swapped = 0;
    const int b0 = pref_first ? bi : bj;
    const int jb0 = pref_first ? bj : bi;
    int occ = atomicAdd(&cnt[b0], 1);
    if (occ < 8) {
        slot = occ * 32 + b0; swapped = pref_first ? 0 : 1;
        jflag[occ * 32 + jb0] = 1;
    } else {
        atomicSub(&cnt[b0], 1);
        const int b1 = pref_first ? bj : bi;
        const int jb1 = pref_first ? bi : bj;
        occ = atomicAdd(&cnt[b1], 1);
        if (occ < 8) {
            slot = occ * 32 + b1; swapped = pref_first ? 1 : 0;
            jflag[occ * 32 + jb1] = 1;
        } else atomicSub(&cnt[b1], 1);
    }
    if (slot >= 0) taken[slot] = 1;
    __syncthreads();
    if (!taken[t]) { int k = atomicAdd(&nfree, 1); sfree[k] = t; }
    __syncthreads();
    if (slot < 0) { int k = atomicAdd(&ovfp, 1); slot = sfree[k]; }

    const uint32_t ii = (uint32_t)(swapped ? j : i);
    const uint32_t jj = (uint32_t)(swapped ? i : j);
    g_sched[r * NPAIR + slot] = ii | (jj << 16);
    g_cs  [r * NPAIR + slot] = make_float2(c, swapped ? -s : s);
}

// ---------------- kernel 2 (fused): build V0|V1 segment rows  +  cast x to fp16 ----------------
// Blocks 0..127: segment 0 (rounds [0,256)) -> g_V0. Blocks 128..255: segment 1 -> g_V1.
// Blocks 256..511: cast x -> fp16. 512 blocks total: full SM coverage + co-residency.
__global__ void __launch_bounds__(256) build_split_kernel(const float4* __restrict__ x4) {
    const int t = threadIdx.x;
    if (blockIdx.x < 256) {
        __shared__ float rows[RPB][N_DIM];
        const int seg   = blockIdx.x >> 7;                  // 0 or 1
        const int obase = (blockIdx.x & 127) * RPB;
        const int r0 = seg ? SEG0_END : 0;
        const int r1 = seg ? NROUND   : SEG0_END;
        float* __restrict__ Vout = seg ? g_V1 : g_V0;
        #pragma unroll
        for (int q = 0; q < RPB; q++) {
            rows[q][t]       = (t == obase + q)       ? 1.0f : 0.0f;
            rows[q][t + 256] = (t + 256 == obase + q) ? 1.0f : 0.0f;
        }
        uint32_t id = g_sched[r0 * NPAIR + t];
        float2   cs = g_cs[r0 * NPAIR + t];
        __syncthreads();
        for (int r = r0; r < r1; r++) {
            const int nidx = (r + 1 < r1) ? (r + 1) * NPAIR + t : r0 * NPAIR + t;
            const uint32_t id_n = g_sched[nidx];
            const float2   cs_n = g_cs[nidx];
            const int i = (int)(id & 0xFFFFu);
            const int j = (int)(id >> 16);
            #pragma unroll
            for (int q = 0; q < RPB; q++) {
                const float ui = rows[q][i];
                const float uj = rows[q][j];
                rows[q][i] = fmaf(cs.x, ui, cs.y * uj);
                rows[q][j] = fmaf(cs.x, uj, -(cs.y * ui));
            }
            __syncthreads();
            id = id_n; cs = cs_n;
        }
        #pragma unroll
        for (int q = 0; q < RPB; q++)
            for (int c = t; c < N_DIM; c += 256)
                Vout[(obase + q) * N_DIM + c] = rows[q][c];
    } else {
        // cast x -> fp16
        const int bs = blockIdx.x - 256;                    // 0..255
        const int base = bs * 8192;                         // 256*8192 = 2^21 float4 exact
        #pragma unroll 4
        for (int k = 0; k < 32; k++) {
            const int idx = base + k * 256 + t;
            const float4 v = x4[idx];
            __half2 a, b;
            a.x = __float2half(v.x); a.y = __float2half(v.y);
            b.x = __float2half(v.z); b.y = __float2half(v.w);
            ((__half2*)g_xh)[2 * idx]     = a;
            ((__half2*)g_xh)[2 * idx + 1] = b;
        }
    }
}

// ---------------- kernel 3: fixup  U = V0 * V1  (fp32, 512^3), cast to fp16 ----------------
// Tile 32(M) x 64(N), 128 threads, 4x4 micro-tile. 128 CTAs, FMA-bound (~5us).
__global__ void __launch_bounds__(128) fixup_kernel() {
    __shared__ float As[32][33];    // [m][k]
    __shared__ float Bs[32][65];    // [k][n]
    const int tid = threadIdx.x;
    const int tx = tid & 15;        // n group (0..15) -> 4 cols
    const int ty = tid >> 4;        // m group (0..7)  -> 4 rows
    const int n0 = blockIdx.x * 64;
    const int m0 = blockIdx.y * 32;
    float acc[4][4] = {};
    for (int kc = 0; kc < N_DIM; kc += 32) {
        #pragma unroll
        for (int l = 0; l < 8; l++) {                       // A: 32x32
            const int idx = tid + l * 128;
            const int row = idx >> 5, k = idx & 31;
            As[row][k] = g_V0[(m0 + row) * N_DIM + kc + k];
        }
        #pragma unroll
        for (int l = 0; l < 16; l++) {                      // B: 32x64
            const int idx = tid + l * 128;
            const int k = idx >> 6, col = idx & 63;
            Bs[k][col] = g_V1[(kc + k) * N_DIM + n0 + col];
        }
        __syncthreads();
        #pragma unroll 8
        for (int kk = 0; kk < 32; kk++) {
            float a[4], b[4];
            #pragma unroll
            for (int i = 0; i < 4; i++) a[i] = As[ty * 4 + i][kk];
            #pragma unroll
            for (int i = 0; i < 4; i++) b[i] = Bs[kk][tx * 4 + i];
            #pragma unroll
            for (int i = 0; i < 4; i++)
                #pragma unroll
                for (int j = 0; j < 4; j++)
                    acc[i][j] = fmaf(a[i], b[j], acc[i][j]);
        }
        __syncthreads();
    }
    #pragma unroll
    for (int i = 0; i < 4; i++)
        #pragma unroll
        for (int j = 0; j < 4; j++)
            g_Uh[(m0 + ty * 4 + i) * N_DIM + n0 + tx * 4 + j] = __float2half(acc[i][j]);
}

// ---------------- kernel 4: single fp16 GEMM out = x @ U^T + bias ----------------
#define KC        64
#define PITCH     144
#define TILE_SB   (128 * PITCH)             // 18432 B
#define STAGE_SB  (2 * TILE_SB)             // A + B = 36864 B
#define NSTAGE    3
#define GEMM_SMEM (NSTAGE * STAGE_SB)       // 110592 B
#define NCHUNK    8

__device__ __forceinline__ void issue_chunk(uint32_t sbase, int i, int m0, int n0, int tid) {
    if (i < NCHUNK) {
        const __half* gA = g_xh + (size_t)m0 * N_DIM + i * KC;
        const __half* gB = g_Uh + (size_t)n0 * N_DIM + i * KC;
        const uint32_t stage = sbase + (uint32_t)(i % NSTAGE) * STAGE_SB;
        #pragma unroll
        for (int tt = 0; tt < 4; tt++) {                    // each tile: 1024 x 16B
            const int idx = tid + tt * 256;
            const int row = idx >> 3, seg = idx & 7;
            const uint32_t soff = (uint32_t)(row * PITCH + seg * 16);
            const size_t goff = (size_t)row * N_DIM + seg * 8;
            cp_async16(stage + soff,           gA + goff);
            cp_async16(stage + TILE_SB + soff, gB + goff);
        }
    }
    asm volatile("cp.async.commit_group;" ::: "memory");
}

__global__ void __launch_bounds__(256, 2) gemm_kernel(float* __restrict__ out,
                                                      const float* __restrict__ bias) {
    extern __shared__ char smem[];
    const uint32_t sb = smem_u32(smem);
    const int tid   = threadIdx.x;
    const int lane  = tid & 31;
    const int wid   = tid >> 5;
    const int warpM = wid & 3;
    const int warpN = wid >> 2;
    const int n0 = blockIdx.x * 128;
    const int m0 = blockIdx.y * 128;

    float acc[2][8][4];
    #pragma unroll
    for (int a = 0; a < 2; a++)
        #pragma unroll
        for (int b = 0; b < 8; b++)
            #pragma unroll
            for (int c = 0; c < 4; c++) acc[a][b][c] = 0.0f;

    const int lrow = lane & 15;
    const int loct = lane >> 4;

    issue_chunk(sb, 0, m0, n0, tid);
    issue_chunk(sb, 1, m0, n0, tid);

    for (int i = 0; i < NCHUNK; i++) {
        issue_chunk(sb, i + 2, m0, n0, tid);
        asm volatile("cp.async.wait_group 2;" ::: "memory");
        __syncthreads();

        const uint32_t stage = sb + (uint32_t)(i % NSTAGE) * STAGE_SB;
        const uint32_t sA = stage + (uint32_t)((warpM * 32 + lrow) * PITCH);
        const uint32_t sB = stage + TILE_SB + (uint32_t)((warpN * 64 + lrow) * PITCH);

        #pragma unroll
        for (int ks = 0; ks < 4; ks++) {
            const uint32_t koff = (uint32_t)(ks * 32 + loct * 16);
            uint32_t afr[2][4], bfr[4][4];
            #pragma unroll
            for (int mi = 0; mi < 2; mi++)
                ldm_x4(afr[mi], sA + (uint32_t)(mi * 16 * PITCH) + koff);
            #pragma unroll
            for (int nj = 0; nj < 4; nj++)
                ldm_x4(bfr[nj], sB + (uint32_t)(nj * 16 * PITCH) + koff);
            #pragma unroll
            for (int mi = 0; mi < 2; mi++)
                #pragma unroll
                for (int t = 0; t < 8; t++) {
                    const int nj = t >> 1, hl = t & 1;
                    mma16816(acc[mi][t], afr[mi], bfr[nj][hl], bfr[nj][hl + 2]);
                }
        }
        __syncthreads();
    }

    const int rbase = m0 + warpM * 32 + (lane >> 2);
    const int cbase = n0 + warpN * 64 + (lane & 3) * 2;
    #pragma unroll
    for (int t = 0; t < 8; t++) {
        const int col = cbase + t * 8;
        const float2 bv = __ldg((const float2*)&bias[col]);
        #pragma unroll
        for (int mi = 0; mi < 2; mi++) {
            const int r0 = rbase + mi * 16;
            float2 v0, v1;
            v0.x = acc[mi][t][0] + bv.x; v0.y = acc[mi][t][1] + bv.y;
            v1.x = acc[mi][t][2] + bv.x; v1.y = acc[mi][t][3] + bv.y;
            *(float2*)&out[(size_t)r0 * N_DIM + col]       = v0;
            *(float2*)&out[(size_t)(r0 + 8) * N_DIM + col] = v1;
        }
    }
}

// ---------------- launch ----------------
extern "C" void kernel_launch(void* const* d_in, const int* in_sizes, int n_in,
                              void* d_out, int out_size) {
    const float* x = nullptr;
    const float* angles = nullptr;
    const float* bias = nullptr;
    const int*   blocks = nullptr;
    for (int i = 0; i < n_in; i++) {
        const long sz = in_sizes[i];
        if      (sz == (long)BATCH_DIM * N_DIM)  x      = (const float*)d_in[i];
        else if (sz == (long)NROUND * NPAIR)     angles = (const float*)d_in[i];
        else if (sz == (long)N_DIM)              bias   = (const float*)d_in[i];
        else if (sz == (long)NROUND * NPAIR * 2) blocks = (const int*)d_in[i];
    }
    float* out = (float*)d_out;

    sched_kernel<<<NROUND, NPAIR>>>(blocks, angles);
    build_split_kernel<<<512, 256>>>((const float4*)x);
    fixup_kernel<<<dim3(N_DIM / 64, N_DIM / 32), 128>>>();
    cudaFuncSetAttribute(gemm_kernel, cudaFuncAttributeMaxDynamicSharedMemorySize, GEMM_SMEM);
    gemm_kernel<<<dim3(4, 128), 256, GEMM_SMEM>>>(out, bias);
}